// round 2
// baseline (speedup 1.0000x reference)
#include <cuda_runtime.h>

#define Bq  256
#define Tq  2000
#define Fq  80
#define Hq  64
#define G3q 192
#define Oq  29
#define WR  68   // padded weight row stride (floats): conflict-free LDS.128

// Precomputed layer-0 input projection: gx0[b][t][g] (393 MB static device scratch)
__device__ float g_gx0[(size_t)Bq * Tq * G3q];

__device__ __forceinline__ float sigf(float x) {
    return __fdividef(1.0f, 1.0f + __expf(-x));
}

// Blackwell packed f32x2 FMA (PTX-only; ptxas never auto-fuses)
__device__ __forceinline__ float2 ffma2(float2 a, float2 b, float2 c) {
    float2 d;
    asm("fma.rn.f32x2 %0, %1, %2, %3;"
        : "=l"(*reinterpret_cast<unsigned long long*>(&d))
        : "l"(*reinterpret_cast<unsigned long long*>(&a)),
          "l"(*reinterpret_cast<unsigned long long*>(&b)),
          "l"(*reinterpret_cast<unsigned long long*>(&c)));
    return d;
}

// ---------------------------------------------------------------------------
// Kernel 1: gx0 = x @ W_ih0^T + b_ih0   (time-parallel GEMM, t-pair f32x2)
// grid = 256 batches * 4 time-quarters; block = 192 threads (1 thread = 1 gate)
// ---------------------------------------------------------------------------
__global__ __launch_bounds__(192) void gx0_kernel(
    const float* __restrict__ x,
    const float* __restrict__ W_ih0,
    const float* __restrict__ b_ih0)
{
    extern __shared__ float sm[];
    float* Wsh = sm;               // [80][192]  W_ih0 transposed
    float* bsh = Wsh + Fq * G3q;   // [192]
    float* xs  = bsh + G3q;        // [80][20]   x tile transposed

    const int tid    = threadIdx.x;
    const int b      = blockIdx.x >> 2;
    const int t0base = (blockIdx.x & 3) * 500;

    for (int idx = tid; idx < G3q * Fq; idx += 192) {
        int gg = idx / Fq, f = idx % Fq;
        Wsh[f * G3q + gg] = W_ih0[idx];
    }
    if (tid < G3q) bsh[tid] = b_ih0[tid];
    __syncthreads();

    const int g = tid;  // gate index 0..191
    for (int c = 0; c < 25; ++c) {
        int t0 = t0base + c * 20;
        for (int idx = tid; idx < 20 * Fq; idx += 192) {
            int tt = idx / Fq, f = idx % Fq;
            xs[f * 20 + tt] = x[((size_t)b * Tq + t0 + tt) * Fq + f];
        }
        __syncthreads();

        float2 acc[10];  // 10 time-pairs
        float bias = bsh[g];
        #pragma unroll
        for (int i = 0; i < 10; ++i) acc[i] = make_float2(bias, bias);

        #pragma unroll 4
        for (int f = 0; f < Fq; ++f) {
            float w = Wsh[f * G3q + g];
            float2 w2 = make_float2(w, w);
            const float4* xv = reinterpret_cast<const float4*>(&xs[f * 20]);
            #pragma unroll
            for (int q = 0; q < 5; ++q) {
                float4 v = xv[q];
                acc[q * 2 + 0] = ffma2(w2, make_float2(v.x, v.y), acc[q * 2 + 0]);
                acc[q * 2 + 1] = ffma2(w2, make_float2(v.z, v.w), acc[q * 2 + 1]);
            }
        }
        #pragma unroll
        for (int i = 0; i < 10; ++i) {
            g_gx0[((size_t)b * Tq + t0 + 2 * i + 0) * G3q + g] = acc[i].x;
            g_gx0[((size_t)b * Tq + t0 + 2 * i + 1) * G3q + g] = acc[i].y;
        }
        __syncthreads();
    }
}

// ---------------------------------------------------------------------------
// Kernel 2: fused 2-layer GRU recurrence + final FC.
// grid = 128, block = (192, 2): 2 batch elements per block, 1 thread per gate.
// Weights per-gate row-major in SMEM, rows padded to 68 floats (conflict-free
// LDS.128); dot products computed with K-paired fma.rn.f32x2.
// ---------------------------------------------------------------------------
__global__ __launch_bounds__(384) void rnn_kernel(
    const float* __restrict__ h_in,
    const float* __restrict__ W_hh0, const float* __restrict__ b_hh0,
    const float* __restrict__ W_ih1, const float* __restrict__ W_hh1,
    const float* __restrict__ b_ih1, const float* __restrict__ b_hh1,
    const float* __restrict__ W_fc,  const float* __restrict__ b_fc,
    float* __restrict__ out, int write_hidden)
{
    extern __shared__ float sm[];
    float* W0s = sm;                  // [192][68]  W_hh0 rows (padded)
    float* W1s = W0s + G3q * WR;      // [192][68]  W_ih1
    float* W2s = W1s + G3q * WR;      // [192][68]  W_hh1
    float* bh0 = W2s + G3q * WR;      // [192]
    float* bi1 = bh0 + G3q;
    float* bh1 = bi1 + G3q;
    float* h0s = bh1 + G3q;           // [2][64]
    float* h1s = h0s + 2 * Hq;        // [2][64]
    float* gbs = h1s + 2 * Hq;        // [2][192]  r/z scratch

    const int g     = threadIdx.x;            // gate 0..191
    const int sub   = threadIdx.y;            // 0..1
    const int tid   = sub * 192 + g;
    const int batch = blockIdx.x * 2 + sub;

    for (int idx = tid; idx < G3q * Hq; idx += 384) {
        int row = idx >> 6, k = idx & 63;
        W0s[row * WR + k] = W_hh0[idx];
        W1s[row * WR + k] = W_ih1[idx];
        W2s[row * WR + k] = W_hh1[idx];
    }
    if (tid < G3q) { bh0[tid] = b_hh0[tid]; bi1[tid] = b_ih1[tid]; bh1[tid] = b_hh1[tid]; }

    float* h0 = h0s + sub * Hq;
    float* h1 = h1s + sub * Hq;
    float* gb = gbs + sub * G3q;
    if (g < Hq) {
        h0[g] = h_in[batch * Hq + g];
        h1[g] = h_in[Bq * Hq + batch * Hq + g];
    }
    __syncthreads();

    const float4* w0v = reinterpret_cast<const float4*>(&W0s[g * WR]);
    const float4* w1v = reinterpret_cast<const float4*>(&W1s[g * WR]);
    const float4* w2v = reinterpret_cast<const float4*>(&W2s[g * WR]);
    const float4* h0v = reinterpret_cast<const float4*>(h0);
    const float4* h1v = reinterpret_cast<const float4*>(h1);

    const float* gxp = g_gx0 + (size_t)batch * Tq * G3q;
    float gx = gxp[g];  // t = 0

    for (int t = 0; t < Tq; ++t) {
        // prefetch next step's input projection
        float gx_next = (t + 1 < Tq) ? __ldg(&gxp[(size_t)(t + 1) * G3q + g]) : 0.0f;

        // ---- layer 0: acc = W_hh0[g] . h0 + b_hh0[g] ----
        float2 pA = make_float2(bh0[g], 0.0f);
        float2 pB = make_float2(0.0f, 0.0f);
        #pragma unroll
        for (int k4 = 0; k4 < 16; ++k4) {
            float4 w = w0v[k4];
            float4 hv = h0v[k4];
            pA = ffma2(make_float2(w.x, w.y), make_float2(hv.x, hv.y), pA);
            pB = ffma2(make_float2(w.z, w.w), make_float2(hv.z, hv.w), pB);
        }
        float acc = (pA.x + pA.y) + (pB.x + pB.y);

        if (g < 128) gb[g] = sigf(gx + acc);   // r (0..63), z (64..127)
        __syncthreads();
        if (g >= 128) {                         // n gate + in-place h0 update
            int j = g - 128;
            float r = gb[j], z = gb[64 + j];
            float nv = tanhf(gx + r * acc);
            h0[j] = (1.0f - z) * nv + z * h0[j];
        }
        __syncthreads();

        // ---- layer 1: a1 = W_ih1[g] . h0_new + bi1 ; a2 = W_hh1[g] . h1 + bh1 ----
        float2 qA = make_float2(bi1[g], 0.0f), qB = make_float2(0.0f, 0.0f);
        float2 rA = make_float2(bh1[g], 0.0f), rB = make_float2(0.0f, 0.0f);
        #pragma unroll
        for (int k4 = 0; k4 < 16; ++k4) {
            float4 w1 = w1v[k4];
            float4 w2 = w2v[k4];
            float4 u = h0v[k4];
            float4 v = h1v[k4];
            qA = ffma2(make_float2(w1.x, w1.y), make_float2(u.x, u.y), qA);
            rA = ffma2(make_float2(w2.x, w2.y), make_float2(v.x, v.y), rA);
            qB = ffma2(make_float2(w1.z, w1.w), make_float2(u.z, u.w), qB);
            rB = ffma2(make_float2(w2.z, w2.w), make_float2(v.z, v.w), rB);
        }
        float a1 = (qA.x + qA.y) + (qB.x + qB.y);
        float a2 = (rA.x + rA.y) + (rB.x + rB.y);

        if (g < 128) gb[g] = sigf(a1 + a2);
        __syncthreads();
        if (g >= 128) {
            int j = g - 128;
            float r = gb[j], z = gb[64 + j];
            float nv = tanhf(a1 + r * a2);
            h1[j] = (1.0f - z) * nv + z * h1[j];
        }
        __syncthreads();

        gx = gx_next;
    }

    // ---- outputs: logits = relu(h1T) @ W_fc^T + b_fc ; hidden = [h0T, h1T] ----
    if (write_hidden && g < Hq) {
        out[Bq * Oq + batch * Hq + g]           = h0[g];
        out[Bq * Oq + Bq * Hq + batch * Hq + g] = h1[g];
    }
    if (g < Oq) {
        float acc = b_fc[g];
        #pragma unroll
        for (int j = 0; j < Hq; ++j)
            acc = fmaf(fmaxf(h1[j], 0.0f), __ldg(&W_fc[g * Hq + j]), acc);
        out[batch * Oq + g] = acc;
    }
}

// ---------------------------------------------------------------------------
extern "C" void kernel_launch(void* const* d_in, const int* in_sizes, int n_in,
                              void* d_out, int out_size) {
    const float* x     = (const float*)d_in[0];
    const float* h     = (const float*)d_in[1];
    const float* W_ih0 = (const float*)d_in[2];
    const float* W_hh0 = (const float*)d_in[3];
    const float* b_ih0 = (const float*)d_in[4];
    const float* b_hh0 = (const float*)d_in[5];
    const float* W_ih1 = (const float*)d_in[6];
    const float* W_hh1 = (const float*)d_in[7];
    const float* b_ih1 = (const float*)d_in[8];
    const float* b_hh1 = (const float*)d_in[9];
    const float* W_fc  = (const float*)d_in[10];
    const float* b_fc  = (const float*)d_in[11];
    float* out = (float*)d_out;

    const int smem1 = (Fq * G3q + G3q + Fq * 20) * (int)sizeof(float);  // 68,608 B
    const int smem2 = (3 * G3q * WR + 3 * G3q + 4 * Hq + 2 * G3q) * (int)sizeof(float); // ~161.5 KB

    cudaFuncSetAttribute(gx0_kernel, cudaFuncAttributeMaxDynamicSharedMemorySize, smem1);
    cudaFuncSetAttribute(rnn_kernel, cudaFuncAttributeMaxDynamicSharedMemorySize, smem2);

    gx0_kernel<<<Bq * 4, 192, smem1>>>(x, W_ih0, b_ih0);

    int write_hidden = (out_size >= Bq * Oq + 2 * Bq * Hq) ? 1 : 0;
    rnn_kernel<<<Bq / 2, dim3(192, 2), smem2>>>(h, W_hh0, b_hh0,
                                                W_ih1, W_hh1, b_ih1, b_hh1,
                                                W_fc, b_fc, out, write_hidden);
}

// round 3
// speedup vs baseline: 1.6793x; 1.6793x over previous
#include <cuda_runtime.h>

#define Bq  256
#define Tq  2000
#define Fq  80
#define Hq  64
#define G3q 192
#define Oq  29

// Precomputed layer-0 input projection: gx0[b][t][g] (393 MB static device scratch)
__device__ float g_gx0[(size_t)Bq * Tq * G3q];

__device__ __forceinline__ float sigf(float x) {
    return __fdividef(1.0f, 1.0f + __expf(-x));
}

// Blackwell packed f32x2 FMA (PTX-only; ptxas never auto-fuses)
__device__ __forceinline__ float2 ffma2(float2 a, float2 b, float2 c) {
    float2 d;
    asm("fma.rn.f32x2 %0, %1, %2, %3;"
        : "=l"(*reinterpret_cast<unsigned long long*>(&d))
        : "l"(*reinterpret_cast<unsigned long long*>(&a)),
          "l"(*reinterpret_cast<unsigned long long*>(&b)),
          "l"(*reinterpret_cast<unsigned long long*>(&c)));
    return d;
}

// ---------------------------------------------------------------------------
// Kernel 1: gx0 = x @ W_ih0^T + b_ih0   (time-parallel GEMM, t-pair f32x2)
// grid = 256 batches * 4 time-quarters; block = 192 threads (1 thread = 1 gate)
// ---------------------------------------------------------------------------
__global__ __launch_bounds__(192) void gx0_kernel(
    const float* __restrict__ x,
    const float* __restrict__ W_ih0,
    const float* __restrict__ b_ih0)
{
    extern __shared__ float sm[];
    float* Wsh = sm;               // [80][192]  W_ih0 transposed
    float* bsh = Wsh + Fq * G3q;   // [192]
    float* xs  = bsh + G3q;        // [80][20]   x tile transposed

    const int tid    = threadIdx.x;
    const int b      = blockIdx.x >> 2;
    const int t0base = (blockIdx.x & 3) * 500;

    for (int idx = tid; idx < G3q * Fq; idx += 192) {
        int gg = idx / Fq, f = idx % Fq;
        Wsh[f * G3q + gg] = W_ih0[idx];
    }
    if (tid < G3q) bsh[tid] = b_ih0[tid];
    __syncthreads();

    const int g = tid;  // gate index 0..191
    for (int c = 0; c < 25; ++c) {
        int t0 = t0base + c * 20;
        for (int idx = tid; idx < 20 * Fq; idx += 192) {
            int tt = idx / Fq, f = idx % Fq;
            xs[f * 20 + tt] = x[((size_t)b * Tq + t0 + tt) * Fq + f];
        }
        __syncthreads();

        float2 acc[10];  // 10 time-pairs
        float bias = bsh[g];
        #pragma unroll
        for (int i = 0; i < 10; ++i) acc[i] = make_float2(bias, bias);

        #pragma unroll 4
        for (int f = 0; f < Fq; ++f) {
            float w = Wsh[f * G3q + g];
            float2 w2 = make_float2(w, w);
            const float4* xv = reinterpret_cast<const float4*>(&xs[f * 20]);
            #pragma unroll
            for (int q = 0; q < 5; ++q) {
                float4 v = xv[q];
                acc[q * 2 + 0] = ffma2(w2, make_float2(v.x, v.y), acc[q * 2 + 0]);
                acc[q * 2 + 1] = ffma2(w2, make_float2(v.z, v.w), acc[q * 2 + 1]);
            }
        }
        #pragma unroll
        for (int i = 0; i < 10; ++i) {
            g_gx0[((size_t)b * Tq + t0 + 2 * i + 0) * G3q + g] = acc[i].x;
            g_gx0[((size_t)b * Tq + t0 + 2 * i + 1) * G3q + g] = acc[i].y;
        }
        __syncthreads();
    }
}

// ---------------------------------------------------------------------------
// Kernel 2: fused 2-layer GRU + FC, register-resident weights, layer-pipelined.
// grid = 128 blocks (2 batches each), block = 576 threads:
//   tid   0..191  group A: row g of W_hh0   (layer 0, time i)
//   tid 192..383  group B: row g of W_ih1   (layer 1, time i-1)
//   tid 384..575  group C: row g of W_hh1   (layer 1, time i-1)
// Each thread holds its 64-float weight row in registers and computes the dot
// for BOTH batches. SMEM holds only h vectors (broadcast reads) + gate scratch.
// ---------------------------------------------------------------------------
__global__ __launch_bounds__(576, 1) void rnn_kernel(
    const float* __restrict__ h_in,
    const float* __restrict__ W_hh0, const float* __restrict__ b_hh0,
    const float* __restrict__ W_ih1, const float* __restrict__ W_hh1,
    const float* __restrict__ b_ih1, const float* __restrict__ b_hh1,
    const float* __restrict__ W_fc,  const float* __restrict__ b_fc,
    float* __restrict__ out, int write_hidden)
{
    __shared__ float h0s[2][2][Hq];   // [parity][batch][64]
    __shared__ float h1s[2][Hq];      // [batch][64]
    __shared__ float smA[2][128];     // layer0 r,z
    __shared__ float smB[2][128];     // layer1 r,z
    __shared__ float smC[2][G3q];     // layer1 gh (a2)

    const int tid = threadIdx.x;
    const int grp = tid / G3q;        // 0=A, 1=B, 2=C
    const int g   = tid - grp * G3q;  // row 0..191
    const int b0  = blockIdx.x * 2;
    const int b1  = b0 + 1;

    // --- load this thread's weight row into registers ---
    const float* Wsrc = (grp == 0) ? W_hh0 : (grp == 1) ? W_ih1 : W_hh1;
    float4 w[16];
    #pragma unroll
    for (int i = 0; i < 16; ++i)
        w[i] = reinterpret_cast<const float4*>(Wsrc)[g * 16 + i];
    const float bias = (grp == 0) ? b_hh0[g] : (grp == 1) ? b_ih1[g] : b_hh1[g];

    // --- init hidden state (parity 0) ---
    if (tid < Hq)            h0s[0][0][tid]       = h_in[b0 * Hq + tid];
    else if (tid < 2 * Hq)   h0s[0][1][tid - 64]  = h_in[b1 * Hq + tid - 64];
    else if (tid < 3 * Hq)   h1s[0][tid - 128]    = h_in[Bq * Hq + b0 * Hq + tid - 128];
    else if (tid < 4 * Hq)   h1s[1][tid - 192]    = h_in[Bq * Hq + b1 * Hq + tid - 192];
    __syncthreads();

    const float* gxp0 = g_gx0 + (size_t)b0 * Tq * G3q + g;
    const float* gxp1 = g_gx0 + (size_t)b1 * Tq * G3q + g;
    float gxA0 = 0.0f, gxA1 = 0.0f;
    if (grp == 0) { gxA0 = gxp0[0]; gxA1 = gxp1[0]; }

    for (int i = 0; i <= Tq; ++i) {
        const int p = i & 1;

        // prefetch next step's input projection (group A)
        float nx0 = 0.0f, nx1 = 0.0f;
        if (grp == 0 && i + 1 < Tq) {
            nx0 = __ldg(gxp0 + (size_t)(i + 1) * G3q);
            nx1 = __ldg(gxp1 + (size_t)(i + 1) * G3q);
        }

        // --- dot products (both batches) ---
        const float* hv0 = (grp == 2) ? h1s[0] : h0s[p][0];
        const float* hv1 = (grp == 2) ? h1s[1] : h0s[p][1];
        float2 aA0 = make_float2(bias, 0.0f), aB0 = make_float2(0.0f, 0.0f);
        float2 aA1 = make_float2(bias, 0.0f), aB1 = make_float2(0.0f, 0.0f);
        #pragma unroll
        for (int k = 0; k < 16; ++k) {
            float4 wv = w[k];
            float4 u  = reinterpret_cast<const float4*>(hv0)[k];
            float4 v  = reinterpret_cast<const float4*>(hv1)[k];
            aA0 = ffma2(make_float2(wv.x, wv.y), make_float2(u.x, u.y), aA0);
            aB0 = ffma2(make_float2(wv.z, wv.w), make_float2(u.z, u.w), aB0);
            aA1 = ffma2(make_float2(wv.x, wv.y), make_float2(v.x, v.y), aA1);
            aB1 = ffma2(make_float2(wv.z, wv.w), make_float2(v.z, v.w), aB1);
        }
        float d0 = (aA0.x + aA0.y) + (aB0.x + aB0.y);
        float d1 = (aA1.x + aA1.y) + (aB1.x + aB1.y);

        if (grp == 0) {
            // ---- layer 0, time i (active for i < Tq) ----
            if (i < Tq && g < 128) {
                smA[0][g] = sigf(gxA0 + d0);
                smA[1][g] = sigf(gxA1 + d1);
            }
            asm volatile("bar.sync 1, 192;" ::: "memory");
            if (i < Tq && g >= 128) {
                int j = g - 128;
                float r0 = smA[0][j], z0 = smA[0][64 + j];
                float r1 = smA[1][j], z1 = smA[1][64 + j];
                float n0 = tanhf(gxA0 + r0 * d0);
                float n1 = tanhf(gxA1 + r1 * d1);
                h0s[p ^ 1][0][j] = (1.0f - z0) * n0 + z0 * h0s[p][0][j];
                h0s[p ^ 1][1][j] = (1.0f - z1) * n1 + z1 * h0s[p][1][j];
            }
            gxA0 = nx0; gxA1 = nx1;
        } else {
            // ---- layer 1, time i-1 (active for i > 0) ----
            if (grp == 2) { smC[0][g] = d0; smC[1][g] = d1; }
            asm volatile("bar.sync 2, 384;" ::: "memory");
            if (grp == 1 && g < 128 && i > 0) {
                smB[0][g] = sigf(d0 + smC[0][g]);
                smB[1][g] = sigf(d1 + smC[1][g]);
            }
            asm volatile("bar.sync 2, 384;" ::: "memory");
            if (grp == 1 && g >= 128 && i > 0) {
                int j = g - 128;
                float r0 = smB[0][j], z0 = smB[0][64 + j];
                float r1 = smB[1][j], z1 = smB[1][64 + j];
                float n0 = tanhf(d0 + r0 * smC[0][g]);
                float n1 = tanhf(d1 + r1 * smC[1][g]);
                h1s[0][j] = (1.0f - z0) * n0 + z0 * h1s[0][j];
                h1s[1][j] = (1.0f - z1) * n1 + z1 * h1s[1][j];
            }
        }
        __syncthreads();
    }

    // ---- epilogue ----
    const int pf = Tq & 1;  // parity holding h0^(T)
    if (write_hidden && tid < 2 * Hq) {
        int b = tid >> 6, j = tid & 63;
        out[Bq * Oq + (b0 + b) * Hq + j]           = h0s[pf][b][j];
        out[Bq * Oq + Bq * Hq + (b0 + b) * Hq + j] = h1s[b][j];
    }
    if (tid < 2 * Oq) {
        int b = tid / Oq, o = tid - b * Oq;
        float acc = b_fc[o];
        #pragma unroll
        for (int j = 0; j < Hq; ++j)
            acc = fmaf(fmaxf(h1s[b][j], 0.0f), __ldg(&W_fc[o * Hq + j]), acc);
        out[(b0 + b) * Oq + o] = acc;
    }
}

// ---------------------------------------------------------------------------
extern "C" void kernel_launch(void* const* d_in, const int* in_sizes, int n_in,
                              void* d_out, int out_size) {
    const float* x     = (const float*)d_in[0];
    const float* h     = (const float*)d_in[1];
    const float* W_ih0 = (const float*)d_in[2];
    const float* W_hh0 = (const float*)d_in[3];
    const float* b_ih0 = (const float*)d_in[4];
    const float* b_hh0 = (const float*)d_in[5];
    const float* W_ih1 = (const float*)d_in[6];
    const float* W_hh1 = (const float*)d_in[7];
    const float* b_ih1 = (const float*)d_in[8];
    const float* b_hh1 = (const float*)d_in[9];
    const float* W_fc  = (const float*)d_in[10];
    const float* b_fc  = (const float*)d_in[11];
    float* out = (float*)d_out;

    const int smem1 = (Fq * G3q + G3q + Fq * 20) * (int)sizeof(float);  // 68,608 B

    cudaFuncSetAttribute(gx0_kernel, cudaFuncAttributeMaxDynamicSharedMemorySize, smem1);

    gx0_kernel<<<Bq * 4, 192, smem1>>>(x, W_ih0, b_ih0);

    int write_hidden = (out_size >= Bq * Oq + 2 * Bq * Hq) ? 1 : 0;
    rnn_kernel<<<Bq / 2, 576>>>(h, W_hh0, b_hh0,
                                W_ih1, W_hh1, b_ih1, b_hh1,
                                W_fc, b_fc, out, write_hidden);
}